// round 11
// baseline (speedup 1.0000x reference)
#include <cuda_runtime.h>
#include <cuda_bf16.h>
#include <math.h>

// Problem constants (from reference)
#define N_NODES 100000
#define IN_F    512
#define OUT_F   256
#define F4      (OUT_F / 4)   // 64 float4 per node row

// Scratch in device globals (allocation inside kernel_launch is forbidden)
__device__ float g_H[(size_t)N_NODES * OUT_F];   // tanh(X @ W)
__device__ float g_T[(size_t)N_NODES * OUT_F];   // after first spmm
__device__ int   g_rowptr[N_NODES + 1];

// ---------------------------------------------------------------------------
// Packed f32x2 helpers (Blackwell: FFMA2 only reachable via PTX fma.rn.f32x2)
// ---------------------------------------------------------------------------
__device__ __forceinline__ unsigned long long fma2(unsigned long long a,
                                                   unsigned long long b,
                                                   unsigned long long c) {
    unsigned long long d;
    asm("fma.rn.f32x2 %0, %1, %2, %3;" : "=l"(d) : "l"(a), "l"(b), "l"(c));
    return d;
}
__device__ __forceinline__ unsigned long long bcast2(float x) {
    unsigned long long p;
    asm("mov.b64 %0, {%1, %2};" : "=l"(p) : "f"(x), "f"(x));
    return p;
}
__device__ __forceinline__ void unpack2(unsigned long long p, float& lo, float& hi) {
    asm("mov.b64 {%0, %1}, %2;" : "=f"(lo), "=f"(hi) : "l"(p));
}

// ---------------------------------------------------------------------------
// Build CSR row_ptr from sorted COO row array via binary search per node.
// ---------------------------------------------------------------------------
__global__ void build_rowptr_kernel(const int* __restrict__ row, int E) {
    int i = blockIdx.x * blockDim.x + threadIdx.x;
    if (i > N_NODES) return;
    int lo = 0, hi = E;
    while (lo < hi) {
        int mid = (lo + hi) >> 1;
        if (row[mid] < i) lo = mid + 1; else hi = mid;
    }
    g_rowptr[i] = lo;
}

// ---------------------------------------------------------------------------
// C = tanh(A[M,512] @ W[512,256])  -> g_H
// 128x64 block tile, BK=8, 256 threads, 8x4 microtile computed as 4x4
// row-paired f32x2 packed FMAs.
// ---------------------------------------------------------------------------
#define BM 128
#define BN 64
#define BK 8
#define TM 8
#define TN 4

union F4U { float4 f; unsigned long long u[2]; };

__global__ __launch_bounds__(256, 2)
void gemm_tanh_kernel(const float* __restrict__ A, const float* __restrict__ W, int M) {
    __shared__ float As[BK][BM];
    __shared__ float Bs[BK][BN];

    const int tid = threadIdx.x;            // 0..255
    const int bm  = blockIdx.x * BM;
    const int bn  = blockIdx.y * BN;
    const int ty  = tid >> 4;               // 0..15  (row group: 8 rows each)
    const int tx  = tid & 15;               // 0..15  (col group: 4 cols each)

    // A load map: each thread loads a float4 along K
    const int arow  = tid >> 1;             // 0..127
    const int acol  = (tid & 1) * 4;        // 0 or 4
    const int agrow = bm + arow;
    const bool avalid = (agrow < M);
    const float* Abase = A + (size_t)agrow * IN_F + acol;

    // B load map (threads 0..127): float4 of W
    const int brow = tid >> 4;              // 0..7 for tid<128
    const int bcol = (tid & 15) * 4;

    // 4 row-pairs x 4 cols packed accumulators ({0,0} bit pattern == 0ull)
    unsigned long long accp[TM / 2][TN];
    #pragma unroll
    for (int i = 0; i < TM / 2; i++)
        #pragma unroll
        for (int j = 0; j < TN; j++) accp[i][j] = 0ull;

    for (int k0 = 0; k0 < IN_F; k0 += BK) {
        // load A tile (transposed into As[k][m])
        float4 av = avalid ? *(const float4*)(Abase + k0)
                           : make_float4(0.f, 0.f, 0.f, 0.f);
        As[acol + 0][arow] = av.x;
        As[acol + 1][arow] = av.y;
        As[acol + 2][arow] = av.z;
        As[acol + 3][arow] = av.w;

        // load B tile
        if (tid < 128) {
            float4 bv = *(const float4*)(W + (size_t)(k0 + brow) * OUT_F + bn + bcol);
            *(float4*)&Bs[brow][bcol] = bv;
        }
        __syncthreads();

        #pragma unroll
        for (int k = 0; k < BK; k++) {
            // a: 8 consecutive floats -> 4 natural {even,odd} 64-bit pairs
            F4U ua0, ua1;
            ua0.f = *(const float4*)&As[k][ty * TM];
            ua1.f = *(const float4*)&As[k][ty * TM + 4];
            unsigned long long apk[4];
            apk[0] = ua0.u[0]; apk[1] = ua0.u[1];
            apk[2] = ua1.u[0]; apk[3] = ua1.u[1];

            // b: 4 floats, broadcast-packed
            float4 bv = *(const float4*)&Bs[k][tx * TN];
            unsigned long long bb[4];
            bb[0] = bcast2(bv.x); bb[1] = bcast2(bv.y);
            bb[2] = bcast2(bv.z); bb[3] = bcast2(bv.w);

            #pragma unroll
            for (int i = 0; i < 4; i++)
                #pragma unroll
                for (int j = 0; j < 4; j++)
                    accp[i][j] = fma2(apk[i], bb[j], accp[i][j]);
        }
        __syncthreads();
    }

    // store with tanh: accp[i][j] holds rows (ty*TM+2i, ty*TM+2i+1), col tx*TN+j
    #pragma unroll
    for (int i = 0; i < 4; i++) {
        const int r0 = bm + ty * TM + 2 * i;
        float lo[4], hi[4];
        #pragma unroll
        for (int j = 0; j < 4; j++) unpack2(accp[i][j], lo[j], hi[j]);
        if (r0 < M) {
            float4 v;
            v.x = tanhf(lo[0]); v.y = tanhf(lo[1]);
            v.z = tanhf(lo[2]); v.w = tanhf(lo[3]);
            *(float4*)&g_H[(size_t)r0 * OUT_F + bn + tx * TN] = v;
        }
        if (r0 + 1 < M) {
            float4 v;
            v.x = tanhf(hi[0]); v.y = tanhf(hi[1]);
            v.z = tanhf(hi[2]); v.w = tanhf(hi[3]);
            *(float4*)&g_H[(size_t)(r0 + 1) * OUT_F + bn + tx * TN] = v;
        }
    }
}

// ---------------------------------------------------------------------------
// SpMM: y[i,:] = sum_{e in [rowptr[i], rowptr[i+1])} vals[e] * x[col[e], :]
// 128-thread CTA handles 2 nodes; each 64-thread slice owns one node, each
// thread owns one float4 of the 256-wide row. Edge loop unrolled x4 with
// independent accumulators to raise MLP_eff (B300: lat/MLP + C model).
// phase 0: x = g_H, y = g_T ; phase 1: x = g_T, y = out
// ---------------------------------------------------------------------------
#define NODES_PER_CTA 2

__global__ __launch_bounds__(64 * NODES_PER_CTA)
void spmm_kernel(const int* __restrict__ col, const float* __restrict__ vals,
                 int phase, float* __restrict__ out) {
    const int node = blockIdx.x * NODES_PER_CTA + (threadIdx.x >> 6);
    const int t = threadIdx.x & 63;         // 0..63  (float4 lane within row)
    if (node >= N_NODES) return;

    const float4* __restrict__ x = (phase == 0) ? (const float4*)g_H
                                                : (const float4*)g_T;
    float4* __restrict__ y = (phase == 0) ? (float4*)g_T
                                          : (float4*)out;

    const int s = g_rowptr[node];
    const int e = g_rowptr[node + 1];
    const int n = e - s;

    float4 a0 = make_float4(0.f, 0.f, 0.f, 0.f);
    float4 a1 = make_float4(0.f, 0.f, 0.f, 0.f);
    float4 a2 = make_float4(0.f, 0.f, 0.f, 0.f);
    float4 a3 = make_float4(0.f, 0.f, 0.f, 0.f);

    int i = s;
    const int n4 = s + (n & ~3);
    for (; i < n4; i += 4) {
        // front-batch all loads for 4 edges (raise MLP_eff)
        const float v0 = __ldg(vals + i + 0);
        const float v1 = __ldg(vals + i + 1);
        const float v2 = __ldg(vals + i + 2);
        const float v3 = __ldg(vals + i + 3);
        const int   c0 = __ldg(col + i + 0);
        const int   c1 = __ldg(col + i + 1);
        const int   c2 = __ldg(col + i + 2);
        const int   c3 = __ldg(col + i + 3);
        const float4 b0 = x[(size_t)c0 * F4 + t];
        const float4 b1 = x[(size_t)c1 * F4 + t];
        const float4 b2 = x[(size_t)c2 * F4 + t];
        const float4 b3 = x[(size_t)c3 * F4 + t];
        a0.x += v0 * b0.x; a0.y += v0 * b0.y; a0.z += v0 * b0.z; a0.w += v0 * b0.w;
        a1.x += v1 * b1.x; a1.y += v1 * b1.y; a1.z += v1 * b1.z; a1.w += v1 * b1.w;
        a2.x += v2 * b2.x; a2.y += v2 * b2.y; a2.z += v2 * b2.z; a2.w += v2 * b2.w;
        a3.x += v3 * b3.x; a3.y += v3 * b3.y; a3.z += v3 * b3.z; a3.w += v3 * b3.w;
    }
    for (; i < e; i++) {
        const float v = __ldg(vals + i);
        const int   c = __ldg(col + i);
        const float4 b = x[(size_t)c * F4 + t];
        a0.x += v * b.x; a0.y += v * b.y; a0.z += v * b.z; a0.w += v * b.w;
    }

    float4 acc;
    acc.x = (a0.x + a1.x) + (a2.x + a3.x);
    acc.y = (a0.y + a1.y) + (a2.y + a3.y);
    acc.z = (a0.z + a1.z) + (a2.z + a3.z);
    acc.w = (a0.w + a1.w) + (a2.w + a3.w);
    y[(size_t)node * F4 + t] = acc;
}

// ---------------------------------------------------------------------------
extern "C" void kernel_launch(void* const* d_in, const int* in_sizes, int n_in,
                              void* d_out, int out_size) {
    const float* features = (const float*)d_in[0];   // [N_NODES, 512]
    const float* weight   = (const float*)d_in[1];   // [512, 256]
    const int*   row      = (const int*)  d_in[2];   // [E] sorted
    const int*   col      = (const int*)  d_in[3];   // [E]
    const float* vals     = (const float*)d_in[4];   // [E]
    float*       out      = (float*)d_out;           // [N_NODES, 256]

    const int M = in_sizes[0] / IN_F;   // 100000
    const int E = in_sizes[2];          // 1600000

    // 1) CSR row_ptr
    {
        int threads = 256;
        int blocks = (N_NODES + 1 + threads - 1) / threads;
        build_rowptr_kernel<<<blocks, threads>>>(row, E);
    }

    // 2) H = tanh(X @ W)
    {
        dim3 grid((M + BM - 1) / BM, OUT_F / BN);
        gemm_tanh_kernel<<<grid, 256>>>(features, weight, M);
    }

    // 3) T = A @ H ; 4) out = A @ T
    const int spmm_blocks = (N_NODES + NODES_PER_CTA - 1) / NODES_PER_CTA;
    spmm_kernel<<<spmm_blocks, 64 * NODES_PER_CTA>>>(col, vals, 0, out);
    spmm_kernel<<<spmm_blocks, 64 * NODES_PER_CTA>>>(col, vals, 1, out);
}

// round 14
// speedup vs baseline: 1.1140x; 1.1140x over previous
#include <cuda_runtime.h>
#include <cuda_bf16.h>
#include <math.h>
#include <stdint.h>

// Problem constants
#define N_NODES 100000
#define IN_F    512
#define OUT_F   256
#define F4      (OUT_F / 4)

// Scratch in device globals (allocation anywhere is forbidden)
__device__ float g_H[(size_t)N_NODES * OUT_F];
__device__ float g_T[(size_t)N_NODES * OUT_F];
__device__ int   g_rowptr[N_NODES + 1];

// ---------------------------------------------------------------------------
// Packed f32x2 helpers (FFMA2: 2x fp32 FMA per issue; PTX-only pattern)
// ---------------------------------------------------------------------------
__device__ __forceinline__ unsigned long long fma2(unsigned long long a,
                                                   unsigned long long b,
                                                   unsigned long long c) {
    unsigned long long d;
    asm("fma.rn.f32x2 %0, %1, %2, %3;" : "=l"(d) : "l"(a), "l"(b), "l"(c));
    return d;
}
__device__ __forceinline__ unsigned long long bcast2(float x) {
    unsigned long long p;
    asm("mov.b64 %0, {%1, %2};" : "=l"(p) : "f"(x), "f"(x));
    return p;
}
__device__ __forceinline__ void unpack2(unsigned long long p, float& lo, float& hi) {
    asm("mov.b64 {%0, %1}, %2;" : "=f"(lo), "=f"(hi) : "l"(p));
}

union F4U { float4 f; unsigned long long u[2]; };

// ---------------------------------------------------------------------------
// CSR row_ptr via binary search (row sorted)
// ---------------------------------------------------------------------------
__global__ void build_rowptr_kernel(const int* __restrict__ row, int E) {
    int i = blockIdx.x * blockDim.x + threadIdx.x;
    if (i > N_NODES) return;
    int lo = 0, hi = E;
    while (lo < hi) {
        int mid = (lo + hi) >> 1;
        if (row[mid] < i) lo = mid + 1; else hi = mid;
    }
    g_rowptr[i] = lo;
}

// ---------------------------------------------------------------------------
// g_H = tanh(A[M,512] @ W[512,256])
// 128x128 block tile, BK=16, 256 threads, 8x8 microtile as 4 row-pairs x 8
// cols of packed f32x2 FMAs. Double-buffered smem, register prefetch,
// one __syncthreads per K-chunk.
// ---------------------------------------------------------------------------
#define BM 128
#define BN 128
#define BK 16
#define NCH (IN_F / BK)   // 32

__global__ __launch_bounds__(256, 2)
void gemm_tanh_kernel(const float* __restrict__ A, const float* __restrict__ W, int M) {
    __shared__ float As[2][BK][BM + 4];   // +4 pad spreads transpose-store banks
    __shared__ float Bs[2][BK][BN];

    const int tid = threadIdx.x;          // 0..255
    const int bm  = blockIdx.x * BM;
    const int bn  = blockIdx.y * BN;
    const int ty  = tid >> 4;             // 0..15 (row group of 8)
    const int tx  = tid & 15;             // 0..15 (col group of 8)

    // A load map (per chunk: 128 rows x 16 k = 512 float4; 2 per thread)
    const int ar  = tid >> 2;             // p=0: rows 0..63 ; p=1: +64
    const int ac4 = (tid & 3) << 2;       // k-offset 0,4,8,12
    // B load map (per chunk: 16 k x 128 n = 512 float4; 2 per thread)
    const int bk  = tid >> 5;             // p=0: k 0..7 ; p=1: +8
    const int bc4 = (tid & 31) << 2;      // n-offset 0..124

    float4 pa[2], pb[2];

    // ---- prologue: load chunk 0 into buffer 0 ----
    #pragma unroll
    for (int p = 0; p < 2; p++) {
        int r = p * 64 + ar;
        pa[p] = (bm + r < M) ? *(const float4*)(A + (size_t)(bm + r) * IN_F + ac4)
                             : make_float4(0.f, 0.f, 0.f, 0.f);
        int kr = p * 8 + bk;
        pb[p] = *(const float4*)(W + (size_t)kr * OUT_F + bn + bc4);
    }
    #pragma unroll
    for (int p = 0; p < 2; p++) {
        int r = p * 64 + ar;
        As[0][ac4 + 0][r] = pa[p].x;
        As[0][ac4 + 1][r] = pa[p].y;
        As[0][ac4 + 2][r] = pa[p].z;
        As[0][ac4 + 3][r] = pa[p].w;
        int kr = p * 8 + bk;
        *(float4*)&Bs[0][kr][bc4] = pb[p];
    }
    __syncthreads();

    unsigned long long accp[4][8];
    #pragma unroll
    for (int i = 0; i < 4; i++)
        #pragma unroll
        for (int j = 0; j < 8; j++) accp[i][j] = 0ull;

    for (int ch = 0; ch < NCH; ch++) {
        const int cur = ch & 1;

        // prefetch next chunk into registers (hidden under compute)
        if (ch + 1 < NCH) {
            const int k0 = (ch + 1) * BK;
            #pragma unroll
            for (int p = 0; p < 2; p++) {
                int r = p * 64 + ar;
                pa[p] = (bm + r < M)
                      ? *(const float4*)(A + (size_t)(bm + r) * IN_F + k0 + ac4)
                      : make_float4(0.f, 0.f, 0.f, 0.f);
                int kr = p * 8 + bk;
                pb[p] = *(const float4*)(W + (size_t)(k0 + kr) * OUT_F + bn + bc4);
            }
        }

        // compute on current buffer
        #pragma unroll
        for (int k = 0; k < BK; k++) {
            F4U ua0, ua1;
            ua0.f = *(const float4*)&As[cur][k][ty * 8];
            ua1.f = *(const float4*)&As[cur][k][ty * 8 + 4];
            unsigned long long apk[4];
            apk[0] = ua0.u[0]; apk[1] = ua0.u[1];
            apk[2] = ua1.u[0]; apk[3] = ua1.u[1];

            float4 b0 = *(const float4*)&Bs[cur][k][tx * 8];
            float4 b1 = *(const float4*)&Bs[cur][k][tx * 8 + 4];
            unsigned long long bb[8];
            bb[0] = bcast2(b0.x); bb[1] = bcast2(b0.y);
            bb[2] = bcast2(b0.z); bb[3] = bcast2(b0.w);
            bb[4] = bcast2(b1.x); bb[5] = bcast2(b1.y);
            bb[6] = bcast2(b1.z); bb[7] = bcast2(b1.w);

            #pragma unroll
            for (int i = 0; i < 4; i++)
                #pragma unroll
                for (int j = 0; j < 8; j++)
                    accp[i][j] = fma2(apk[i], bb[j], accp[i][j]);
        }

        // store prefetched chunk into the other buffer, then one sync
        if (ch + 1 < NCH) {
            const int nxt = cur ^ 1;
            #pragma unroll
            for (int p = 0; p < 2; p++) {
                int r = p * 64 + ar;
                As[nxt][ac4 + 0][r] = pa[p].x;
                As[nxt][ac4 + 1][r] = pa[p].y;
                As[nxt][ac4 + 2][r] = pa[p].z;
                As[nxt][ac4 + 3][r] = pa[p].w;
                int kr = p * 8 + bk;
                *(float4*)&Bs[nxt][kr][bc4] = pb[p];
            }
            __syncthreads();
        }
    }

    // ---- epilogue: tanh + store; acc[i][j] = rows (ty*8+2i, +1), col tx*8+j
    #pragma unroll
    for (int i = 0; i < 4; i++) {
        const int r0 = bm + ty * 8 + 2 * i;
        float lo[8], hi[8];
        #pragma unroll
        for (int j = 0; j < 8; j++) unpack2(accp[i][j], lo[j], hi[j]);
        if (r0 < M) {
            float* dst = g_H + (size_t)r0 * OUT_F + bn + tx * 8;
            float4 v0, v1;
            v0.x = tanhf(lo[0]); v0.y = tanhf(lo[1]);
            v0.z = tanhf(lo[2]); v0.w = tanhf(lo[3]);
            v1.x = tanhf(lo[4]); v1.y = tanhf(lo[5]);
            v1.z = tanhf(lo[6]); v1.w = tanhf(lo[7]);
            *(float4*)dst = v0;
            *(float4*)(dst + 4) = v1;
        }
        if (r0 + 1 < M) {
            float* dst = g_H + (size_t)(r0 + 1) * OUT_F + bn + tx * 8;
            float4 v0, v1;
            v0.x = tanhf(hi[0]); v0.y = tanhf(hi[1]);
            v0.z = tanhf(hi[2]); v0.w = tanhf(hi[3]);
            v1.x = tanhf(hi[4]); v1.y = tanhf(hi[5]);
            v1.z = tanhf(hi[6]); v1.w = tanhf(hi[7]);
            *(float4*)dst = v0;
            *(float4*)(dst + 4) = v1;
        }
    }
}

// ---------------------------------------------------------------------------
// SpMM (unchanged from the 1077us pass): 2 nodes per 128-thread CTA,
// 4-way MLP edge unroll.
// ---------------------------------------------------------------------------
#define NODES_PER_CTA 2

__global__ __launch_bounds__(64 * NODES_PER_CTA)
void spmm_kernel(const int* __restrict__ col, const float* __restrict__ vals,
                 int phase, float* __restrict__ out) {
    const int node = blockIdx.x * NODES_PER_CTA + (threadIdx.x >> 6);
    const int t = threadIdx.x & 63;
    if (node >= N_NODES) return;

    const float4* __restrict__ x = (phase == 0) ? (const float4*)g_H
                                                : (const float4*)g_T;
    float4* __restrict__ y = (phase == 0) ? (float4*)g_T
                                          : (float4*)out;

    const int s = g_rowptr[node];
    const int e = g_rowptr[node + 1];
    const int n = e - s;

    float4 a0 = make_float4(0.f, 0.f, 0.f, 0.f);
    float4 a1 = make_float4(0.f, 0.f, 0.f, 0.f);
    float4 a2 = make_float4(0.f, 0.f, 0.f, 0.f);
    float4 a3 = make_float4(0.f, 0.f, 0.f, 0.f);

    int i = s;
    const int n4 = s + (n & ~3);
    for (; i < n4; i += 4) {
        const float v0 = __ldg(vals + i + 0);
        const float v1 = __ldg(vals + i + 1);
        const float v2 = __ldg(vals + i + 2);
        const float v3 = __ldg(vals + i + 3);
        const int   c0 = __ldg(col + i + 0);
        const int   c1 = __ldg(col + i + 1);
        const int   c2 = __ldg(col + i + 2);
        const int   c3 = __ldg(col + i + 3);
        const float4 b0 = x[(size_t)c0 * F4 + t];
        const float4 b1 = x[(size_t)c1 * F4 + t];
        const float4 b2 = x[(size_t)c2 * F4 + t];
        const float4 b3 = x[(size_t)c3 * F4 + t];
        a0.x += v0 * b0.x; a0.y += v0 * b0.y; a0.z += v0 * b0.z; a0.w += v0 * b0.w;
        a1.x += v1 * b1.x; a1.y += v1 * b1.y; a1.z += v1 * b1.z; a1.w += v1 * b1.w;
        a2.x += v2 * b2.x; a2.y += v2 * b2.y; a2.z += v2 * b2.z; a2.w += v2 * b2.w;
        a3.x += v3 * b3.x; a3.y += v3 * b3.y; a3.z += v3 * b3.z; a3.w += v3 * b3.w;
    }
    for (; i < e; i++) {
        const float v = __ldg(vals + i);
        const int   c = __ldg(col + i);
        const float4 b = x[(size_t)c * F4 + t];
        a0.x += v * b.x; a0.y += v * b.y; a0.z += v * b.z; a0.w += v * b.w;
    }

    float4 acc;
    acc.x = (a0.x + a1.x) + (a2.x + a3.x);
    acc.y = (a0.y + a1.y) + (a2.y + a3.y);
    acc.z = (a0.z + a1.z) + (a2.z + a3.z);
    acc.w = (a0.w + a1.w) + (a2.w + a3.w);
    y[(size_t)node * F4 + t] = acc;
}

// ---------------------------------------------------------------------------
extern "C" void kernel_launch(void* const* d_in, const int* in_sizes, int n_in,
                              void* d_out, int out_size) {
    const float* features = (const float*)d_in[0];   // [N_NODES, 512]
    const float* weight   = (const float*)d_in[1];   // [512, 256]
    const int*   row      = (const int*)  d_in[2];   // [E] sorted
    const int*   col      = (const int*)  d_in[3];   // [E]
    const float* vals     = (const float*)d_in[4];   // [E]
    float*       out      = (float*)d_out;           // [N_NODES, 256]

    const int M = in_sizes[0] / IN_F;   // 100000
    const int E = in_sizes[2];          // 1600000

    // 1) CSR row_ptr
    {
        int threads = 256;
        int blocks = (N_NODES + 1 + threads - 1) / threads;
        build_rowptr_kernel<<<blocks, threads>>>(row, E);
    }

    // 2) H = tanh(X @ W)
    {
        dim3 grid((M + BM - 1) / BM, OUT_F / BN);
        gemm_tanh_kernel<<<grid, 256>>>(features, weight, M);
    }

    // 3) T = A @ H ; 4) out = A @ T
    const int spmm_blocks = (N_NODES + NODES_PER_CTA - 1) / NODES_PER_CTA;
    spmm_kernel<<<spmm_blocks, 64 * NODES_PER_CTA>>>(col, vals, 0, out);
    spmm_kernel<<<spmm_blocks, 64 * NODES_PER_CTA>>>(col, vals, 1, out);
}

// round 16
// speedup vs baseline: 1.2231x; 1.0980x over previous
#include <cuda_runtime.h>
#include <cuda_bf16.h>
#include <math.h>
#include <stdint.h>

// Problem constants
#define N_NODES 100000
#define IN_F    512
#define OUT_F   256
#define F4      (OUT_F / 4)

// Scratch in device globals (allocation anywhere is forbidden)
__device__ float g_H[(size_t)N_NODES * OUT_F];
__device__ float g_T[(size_t)N_NODES * OUT_F];
__device__ int   g_rowptr[N_NODES + 1];

// ---------------------------------------------------------------------------
// Packed f32x2 helpers (FFMA2: 2x fp32 FMA per issue; PTX-only pattern)
// ---------------------------------------------------------------------------
__device__ __forceinline__ unsigned long long fma2(unsigned long long a,
                                                   unsigned long long b,
                                                   unsigned long long c) {
    unsigned long long d;
    asm("fma.rn.f32x2 %0, %1, %2, %3;" : "=l"(d) : "l"(a), "l"(b), "l"(c));
    return d;
}
__device__ __forceinline__ unsigned long long bcast2(float x) {
    unsigned long long p;
    asm("mov.b64 %0, {%1, %2};" : "=l"(p) : "f"(x), "f"(x));
    return p;
}
__device__ __forceinline__ void unpack2(unsigned long long p, float& lo, float& hi) {
    asm("mov.b64 {%0, %1}, %2;" : "=f"(lo), "=f"(hi) : "l"(p));
}

union F4U { float4 f; unsigned long long u[2]; };

// ---------------------------------------------------------------------------
// CSR row_ptr via binary search (row sorted)
// ---------------------------------------------------------------------------
__global__ void build_rowptr_kernel(const int* __restrict__ row, int E) {
    int i = blockIdx.x * blockDim.x + threadIdx.x;
    if (i > N_NODES) return;
    int lo = 0, hi = E;
    while (lo < hi) {
        int mid = (lo + hi) >> 1;
        if (row[mid] < i) lo = mid + 1; else hi = mid;
    }
    g_rowptr[i] = lo;
}

// ---------------------------------------------------------------------------
// g_H = tanh(A[M,512] @ W[512,256])  — UNCHANGED from 967us pass
// 128x128 block tile, BK=16, 256 threads, 8x8 microtile as 4 row-pairs x 8
// cols of packed f32x2 FMAs. Double-buffered smem, register prefetch.
// ---------------------------------------------------------------------------
#define BM 128
#define BN 128
#define BK 16
#define NCH (IN_F / BK)   // 32

__global__ __launch_bounds__(256, 2)
void gemm_tanh_kernel(const float* __restrict__ A, const float* __restrict__ W, int M) {
    __shared__ float As[2][BK][BM + 4];
    __shared__ float Bs[2][BK][BN];

    const int tid = threadIdx.x;
    const int bm  = blockIdx.x * BM;
    const int bn  = blockIdx.y * BN;
    const int ty  = tid >> 4;
    const int tx  = tid & 15;

    const int ar  = tid >> 2;
    const int ac4 = (tid & 3) << 2;
    const int bk  = tid >> 5;
    const int bc4 = (tid & 31) << 2;

    float4 pa[2], pb[2];

    #pragma unroll
    for (int p = 0; p < 2; p++) {
        int r = p * 64 + ar;
        pa[p] = (bm + r < M) ? *(const float4*)(A + (size_t)(bm + r) * IN_F + ac4)
                             : make_float4(0.f, 0.f, 0.f, 0.f);
        int kr = p * 8 + bk;
        pb[p] = *(const float4*)(W + (size_t)kr * OUT_F + bn + bc4);
    }
    #pragma unroll
    for (int p = 0; p < 2; p++) {
        int r = p * 64 + ar;
        As[0][ac4 + 0][r] = pa[p].x;
        As[0][ac4 + 1][r] = pa[p].y;
        As[0][ac4 + 2][r] = pa[p].z;
        As[0][ac4 + 3][r] = pa[p].w;
        int kr = p * 8 + bk;
        *(float4*)&Bs[0][kr][bc4] = pb[p];
    }
    __syncthreads();

    unsigned long long accp[4][8];
    #pragma unroll
    for (int i = 0; i < 4; i++)
        #pragma unroll
        for (int j = 0; j < 8; j++) accp[i][j] = 0ull;

    for (int ch = 0; ch < NCH; ch++) {
        const int cur = ch & 1;

        if (ch + 1 < NCH) {
            const int k0 = (ch + 1) * BK;
            #pragma unroll
            for (int p = 0; p < 2; p++) {
                int r = p * 64 + ar;
                pa[p] = (bm + r < M)
                      ? *(const float4*)(A + (size_t)(bm + r) * IN_F + k0 + ac4)
                      : make_float4(0.f, 0.f, 0.f, 0.f);
                int kr = p * 8 + bk;
                pb[p] = *(const float4*)(W + (size_t)(k0 + kr) * OUT_F + bn + bc4);
            }
        }

        #pragma unroll
        for (int k = 0; k < BK; k++) {
            F4U ua0, ua1;
            ua0.f = *(const float4*)&As[cur][k][ty * 8];
            ua1.f = *(const float4*)&As[cur][k][ty * 8 + 4];
            unsigned long long apk[4];
            apk[0] = ua0.u[0]; apk[1] = ua0.u[1];
            apk[2] = ua1.u[0]; apk[3] = ua1.u[1];

            float4 b0 = *(const float4*)&Bs[cur][k][tx * 8];
            float4 b1 = *(const float4*)&Bs[cur][k][tx * 8 + 4];
            unsigned long long bb[8];
            bb[0] = bcast2(b0.x); bb[1] = bcast2(b0.y);
            bb[2] = bcast2(b0.z); bb[3] = bcast2(b0.w);
            bb[4] = bcast2(b1.x); bb[5] = bcast2(b1.y);
            bb[6] = bcast2(b1.z); bb[7] = bcast2(b1.w);

            #pragma unroll
            for (int i = 0; i < 4; i++)
                #pragma unroll
                for (int j = 0; j < 8; j++)
                    accp[i][j] = fma2(apk[i], bb[j], accp[i][j]);
        }

        if (ch + 1 < NCH) {
            const int nxt = cur ^ 1;
            #pragma unroll
            for (int p = 0; p < 2; p++) {
                int r = p * 64 + ar;
                As[nxt][ac4 + 0][r] = pa[p].x;
                As[nxt][ac4 + 1][r] = pa[p].y;
                As[nxt][ac4 + 2][r] = pa[p].z;
                As[nxt][ac4 + 3][r] = pa[p].w;
                int kr = p * 8 + bk;
                *(float4*)&Bs[nxt][kr][bc4] = pb[p];
            }
            __syncthreads();
        }
    }

    #pragma unroll
    for (int i = 0; i < 4; i++) {
        const int r0 = bm + ty * 8 + 2 * i;
        float lo[8], hi[8];
        #pragma unroll
        for (int j = 0; j < 8; j++) unpack2(accp[i][j], lo[j], hi[j]);
        if (r0 < M) {
            float* dst = g_H + (size_t)r0 * OUT_F + bn + tx * 8;
            float4 v0, v1;
            v0.x = tanhf(lo[0]); v0.y = tanhf(lo[1]);
            v0.z = tanhf(lo[2]); v0.w = tanhf(lo[3]);
            v1.x = tanhf(lo[4]); v1.y = tanhf(lo[5]);
            v1.z = tanhf(lo[6]); v1.w = tanhf(lo[7]);
            *(float4*)dst = v0;
            *(float4*)(dst + 4) = v1;
        }
        if (r0 + 1 < M) {
            float* dst = g_H + (size_t)(r0 + 1) * OUT_F + bn + tx * 8;
            float4 v0, v1;
            v0.x = tanhf(hi[0]); v0.y = tanhf(hi[1]);
            v0.z = tanhf(hi[2]); v0.w = tanhf(hi[3]);
            v1.x = tanhf(hi[4]); v1.y = tanhf(hi[5]);
            v1.z = tanhf(hi[6]); v1.w = tanhf(hi[7]);
            *(float4*)dst = v0;
            *(float4*)(dst + 4) = v1;
        }
    }
}

// ---------------------------------------------------------------------------
// SpMM, feature-blocked: gridDim.y = 2 column halves; per half the gather
// operand footprint is 51 MB (co-fits L2 with streams). 128-thread CTA =
// 4 node-slices x 32 lanes. Streaming stores for y, streaming loads for
// col/vals (keep x resident in L2). 4-way MLP edge unroll.
// phase 0: x = g_H, y = g_T ; phase 1: x = g_T, y = out
// ---------------------------------------------------------------------------
#define SLICES 4

__global__ __launch_bounds__(32 * SLICES)
void spmm_kernel(const int* __restrict__ col, const float* __restrict__ vals,
                 int phase, float* __restrict__ out) {
    const int node = blockIdx.x * SLICES + (threadIdx.x >> 5);
    const int t = (threadIdx.x & 31) + (blockIdx.y << 5);   // float4 lane 0..63
    if (node >= N_NODES) return;

    const float4* __restrict__ x = (phase == 0) ? (const float4*)g_H
                                                : (const float4*)g_T;
    float4* __restrict__ y = (phase == 0) ? (float4*)g_T
                                          : (float4*)out;

    const int s = g_rowptr[node];
    const int e = g_rowptr[node + 1];
    const int n = e - s;

    float4 a0 = make_float4(0.f, 0.f, 0.f, 0.f);
    float4 a1 = make_float4(0.f, 0.f, 0.f, 0.f);
    float4 a2 = make_float4(0.f, 0.f, 0.f, 0.f);
    float4 a3 = make_float4(0.f, 0.f, 0.f, 0.f);

    int i = s;
    const int n4 = s + (n & ~3);
    for (; i < n4; i += 4) {
        const float v0 = __ldcs(vals + i + 0);
        const float v1 = __ldcs(vals + i + 1);
        const float v2 = __ldcs(vals + i + 2);
        const float v3 = __ldcs(vals + i + 3);
        const int   c0 = __ldcs(col + i + 0);
        const int   c1 = __ldcs(col + i + 1);
        const int   c2 = __ldcs(col + i + 2);
        const int   c3 = __ldcs(col + i + 3);
        const float4 b0 = x[(size_t)c0 * F4 + t];
        const float4 b1 = x[(size_t)c1 * F4 + t];
        const float4 b2 = x[(size_t)c2 * F4 + t];
        const float4 b3 = x[(size_t)c3 * F4 + t];
        a0.x += v0 * b0.x; a0.y += v0 * b0.y; a0.z += v0 * b0.z; a0.w += v0 * b0.w;
        a1.x += v1 * b1.x; a1.y += v1 * b1.y; a1.z += v1 * b1.z; a1.w += v1 * b1.w;
        a2.x += v2 * b2.x; a2.y += v2 * b2.y; a2.z += v2 * b2.z; a2.w += v2 * b2.w;
        a3.x += v3 * b3.x; a3.y += v3 * b3.y; a3.z += v3 * b3.z; a3.w += v3 * b3.w;
    }
    for (; i < e; i++) {
        const float v = __ldcs(vals + i);
        const int   c = __ldcs(col + i);
        const float4 b = x[(size_t)c * F4 + t];
        a0.x += v * b.x; a0.y += v * b.y; a0.z += v * b.z; a0.w += v * b.w;
    }

    float4 acc;
    acc.x = (a0.x + a1.x) + (a2.x + a3.x);
    acc.y = (a0.y + a1.y) + (a2.y + a3.y);
    acc.z = (a0.z + a1.z) + (a2.z + a3.z);
    acc.w = (a0.w + a1.w) + (a2.w + a3.w);
    __stcs(&y[(size_t)node * F4 + t], acc);
}

// ---------------------------------------------------------------------------
extern "C" void kernel_launch(void* const* d_in, const int* in_sizes, int n_in,
                              void* d_out, int out_size) {
    const float* features = (const float*)d_in[0];   // [N_NODES, 512]
    const float* weight   = (const float*)d_in[1];   // [512, 256]
    const int*   row      = (const int*)  d_in[2];   // [E] sorted
    const int*   col      = (const int*)  d_in[3];   // [E]
    const float* vals     = (const float*)d_in[4];   // [E]
    float*       out      = (float*)d_out;           // [N_NODES, 256]

    const int M = in_sizes[0] / IN_F;   // 100000
    const int E = in_sizes[2];          // 1600000

    // 1) CSR row_ptr
    {
        int threads = 256;
        int blocks = (N_NODES + 1 + threads - 1) / threads;
        build_rowptr_kernel<<<blocks, threads>>>(row, E);
    }

    // 2) H = tanh(X @ W)
    {
        dim3 grid((M + BM - 1) / BM, OUT_F / BN);
        gemm_tanh_kernel<<<grid, 256>>>(features, weight, M);
    }

    // 3) T = A @ H ; 4) out = A @ T  (each pass feature-blocked into 2 halves)
    {
        dim3 grid((N_NODES + SLICES - 1) / SLICES, 2);
        spmm_kernel<<<grid, 32 * SLICES>>>(col, vals, 0, out);
        spmm_kernel<<<grid, 32 * SLICES>>>(col, vals, 1, out);
    }
}